// round 1
// baseline (speedup 1.0000x reference)
#include <cuda_runtime.h>

// ---------------------------------------------------------------------------
// PatchCore scoring:
//   p = normalize(patch_feats)  [N,C]
//   score[n] = 1 - max_m ( p[n] . (memory[m] * rm[m]) ),  rm[m]=1/(||mem_m||+eps)
//   image = mean(top-k(score))
// ---------------------------------------------------------------------------

#define NPATCH 4096
#define CDIM   176
#define MMEM   131072
#define BLK    128
#define PAD    180                      // smem row stride in floats (45 x 16B, odd -> conflict-free LDS.128)
#define SPLITS 4
#define ROWS_PER_SPLIT (MMEM / SPLITS)  // 32768
#define CHUNKS_PER_SPLIT (ROWS_PER_SPLIT / BLK) // 256
#define C4 (CDIM / 4)                   // 44 float4 per row
#define ENC_NEG_INF 0x007FFFFFu         // enc(-inf)

__device__ float    g_pn[NPATCH * CDIM];   // normalized patches
__device__ float    g_rm[MMEM];            // 1/(||mem row|| + eps)
__device__ unsigned g_max_enc[NPATCH];     // running max of cos-sim, order-encoded

__device__ __forceinline__ unsigned enc_f(float f) {
    unsigned u = __float_as_uint(f);
    return (u & 0x80000000u) ? ~u : (u | 0x80000000u);
}
__device__ __forceinline__ float dec_f(unsigned e) {
    unsigned u = (e & 0x80000000u) ? (e & 0x7FFFFFFFu) : ~e;
    return __uint_as_float(u);
}

// ---------------- prep: normalize patch rows into g_pn ----------------------
__global__ void norm_patches_kernel(const float* __restrict__ in) {
    int warp = (blockIdx.x * blockDim.x + threadIdx.x) >> 5;
    int lane = threadIdx.x & 31;
    if (warp >= NPATCH) return;
    const float* row = in + (size_t)warp * CDIM;
    float v[6];
    float ss = 0.f;
#pragma unroll
    for (int i = 0; i < 6; i++) {
        int c = lane + 32 * i;
        float x = (c < CDIM) ? row[c] : 0.f;
        v[i] = x;
        ss += x * x;
    }
#pragma unroll
    for (int o = 16; o; o >>= 1) ss += __shfl_xor_sync(0xFFFFFFFFu, ss, o);
    float inv = 1.f / (sqrtf(ss) + 1e-6f);
#pragma unroll
    for (int i = 0; i < 6; i++) {
        int c = lane + 32 * i;
        if (c < CDIM) g_pn[(size_t)warp * CDIM + c] = v[i] * inv;
    }
}

// ---------------- prep: reciprocal norms of memory rows ---------------------
__global__ void norm_mem_kernel(const float* __restrict__ mem) {
    int warp = (blockIdx.x * blockDim.x + threadIdx.x) >> 5;
    int lane = threadIdx.x & 31;
    if (warp >= MMEM) return;
    const float* row = mem + (size_t)warp * CDIM;
    float ss = 0.f;
#pragma unroll
    for (int i = 0; i < 6; i++) {
        int c = lane + 32 * i;
        float x = (c < CDIM) ? row[c] : 0.f;
        ss += x * x;
    }
#pragma unroll
    for (int o = 16; o; o >>= 1) ss += __shfl_xor_sync(0xFFFFFFFFu, ss, o);
    if (lane == 0) g_rm[warp] = 1.f / (sqrtf(ss) + 1e-6f);
}

// ---------------- init running max -----------------------------------------
__global__ void init_max_kernel() {
    int i = blockIdx.x * blockDim.x + threadIdx.x;
    if (i < NPATCH) g_max_enc[i] = ENC_NEG_INF;
}

// ---------------- main: 128x128 fp32 GEMM tile with fused row-max -----------
// grid: (NPATCH/BLK, SPLITS), block: 256 threads (16x16), 8x8 per thread
__global__ void __launch_bounds__(256) gemm_max_kernel(const float* __restrict__ mem) {
    extern __shared__ float sh[];
    float* As = sh;                 // [BLK][PAD] normalized patches tile
    float* Bs = sh + BLK * PAD;     // [BLK][PAD] raw memory tile

    const int tid = threadIdx.x;
    const int tx = tid & 15;
    const int ty = tid >> 4;
    const int ptile = blockIdx.x;
    const int split = blockIdx.y;

    // load patch tile once (float4, coalesced)
    for (int idx = tid; idx < BLK * C4; idx += 256) {
        int r = idx / C4, c4 = idx % C4;
        float4 v = *(const float4*)(g_pn + ((size_t)(ptile * BLK + r)) * CDIM + c4 * 4);
        *(float4*)(As + r * PAD + c4 * 4) = v;
    }

    float tmax[8];
#pragma unroll
    for (int i = 0; i < 8; i++) tmax[i] = -3.0e38f;

    const int base = split * ROWS_PER_SPLIT;

#pragma unroll 1
    for (int ch = 0; ch < CHUNKS_PER_SPLIT; ch++) {
        const int rbase = base + ch * BLK;
        __syncthreads();  // As ready (first iter) / previous compute done
        for (int idx = tid; idx < BLK * C4; idx += 256) {
            int r = idx / C4, c4 = idx % C4;
            float4 v = *(const float4*)(mem + ((size_t)(rbase + r)) * CDIM + c4 * 4);
            *(float4*)(Bs + r * PAD + c4 * 4) = v;
        }
        __syncthreads();

        float acc[8][8];
#pragma unroll
        for (int i = 0; i < 8; i++)
#pragma unroll
            for (int j = 0; j < 8; j++) acc[i][j] = 0.f;

#pragma unroll 1
        for (int k4 = 0; k4 < C4; k4++) {
            float4 a[8];
#pragma unroll
            for (int i = 0; i < 8; i++)
                a[i] = *(const float4*)(As + (ty + (i << 4)) * PAD + (k4 << 2));
#pragma unroll
            for (int j = 0; j < 8; j++) {
                float4 b = *(const float4*)(Bs + (tx + (j << 4)) * PAD + (k4 << 2));
#pragma unroll
                for (int i = 0; i < 8; i++) {
                    acc[i][j] = fmaf(a[i].x, b.x, acc[i][j]);
                    acc[i][j] = fmaf(a[i].y, b.y, acc[i][j]);
                    acc[i][j] = fmaf(a[i].z, b.z, acc[i][j]);
                    acc[i][j] = fmaf(a[i].w, b.w, acc[i][j]);
                }
            }
        }

        // epilogue: scale by memory reciprocal norm, fold into running max
#pragma unroll
        for (int j = 0; j < 8; j++) {
            float r = g_rm[rbase + tx + (j << 4)];
#pragma unroll
            for (int i = 0; i < 8; i++)
                tmax[i] = fmaxf(tmax[i], acc[i][j] * r);
        }
    }

    // cross-thread reduction per patch row (rows = ty + 16*i)
    __syncthreads();
    unsigned* red = (unsigned*)sh;
    if (tid < BLK) red[tid] = ENC_NEG_INF;
    __syncthreads();
#pragma unroll
    for (int i = 0; i < 8; i++)
        atomicMax(&red[ty + (i << 4)], enc_f(tmax[i]));
    __syncthreads();
    if (tid < BLK) atomicMax(&g_max_enc[ptile * BLK + tid], red[tid]);
}

// ---------------- finalize: scores + top-k mean ------------------------------
__global__ void finalize_kernel(const int* __restrict__ topk_ptr,
                                float* __restrict__ out, int out_size) {
    __shared__ float sc[NPATCH];
    __shared__ float rv[256];
    __shared__ int   ri[256];
    const int tid = threadIdx.x;

    for (int i = tid; i < NPATCH; i += 256) {
        float s = 1.0f - dec_f(g_max_enc[i]);
        sc[i] = s;
        if (out_size >= NPATCH) out[i] = s;
    }
    __syncthreads();

    int k = topk_ptr ? *topk_ptr : 10;
    if (k < 1) k = 1;
    if (k > NPATCH) k = NPATCH;

    float sum = 0.f;
    for (int p = 0; p < k; p++) {
        float best = -3.0e38f;
        int bi = 0;
        for (int i = tid; i < NPATCH; i += 256)
            if (sc[i] > best) { best = sc[i]; bi = i; }
        rv[tid] = best; ri[tid] = bi;
        __syncthreads();
        for (int s = 128; s > 0; s >>= 1) {
            if (tid < s && rv[tid + s] > rv[tid]) { rv[tid] = rv[tid + s]; ri[tid] = ri[tid + s]; }
            __syncthreads();
        }
        if (tid == 0) { sum += rv[0]; sc[ri[0]] = -3.0e38f; }
        __syncthreads();
    }

    if (tid == 0) {
        float img = sum / (float)k;
        if (out_size >= NPATCH + 1) out[NPATCH] = img;
        else if (out_size < NPATCH && out_size >= 1) out[0] = img;
    }
}

// ---------------------------------------------------------------------------
extern "C" void kernel_launch(void* const* d_in, const int* in_sizes, int n_in,
                              void* d_out, int out_size) {
    const float* patch = (const float*)d_in[0];
    const float* mem   = (const float*)d_in[1];
    const int*   topk  = (n_in >= 3) ? (const int*)d_in[2] : nullptr;
    float* out = (float*)d_out;

    (void)in_sizes;

    norm_patches_kernel<<<(NPATCH * 32 + 255) / 256, 256>>>(patch);
    norm_mem_kernel<<<(MMEM * 32 + 255) / 256, 256>>>(mem);
    init_max_kernel<<<(NPATCH + 255) / 256, 256>>>();

    const int smem_bytes = 2 * BLK * PAD * (int)sizeof(float); // 184320
    cudaFuncSetAttribute(gemm_max_kernel,
                         cudaFuncAttributeMaxDynamicSharedMemorySize, smem_bytes);
    dim3 grid(NPATCH / BLK, SPLITS);
    gemm_max_kernel<<<grid, 256, smem_bytes>>>(mem);

    finalize_kernel<<<1, 256>>>(topk, out, out_size);
}

// round 3
// speedup vs baseline: 12.8767x; 12.8767x over previous
#include <cuda_runtime.h>
#include <cuda_bf16.h>
#include <cstdint>

// ---------------------------------------------------------------------------
// PatchCore scoring via HMMA (mma.sync m16n8k16 bf16, fp32 accum):
//   score[n] = 1 - max_m cos(p_n, mem_m);  image = mean(top-k(score))
// NOTE: harness compiles at target sm_103 (no 'a') -> tcgen05/TMEM illegal.
//       mma.sync + ldmatrix + cp.async.bulk + mbarrier are family-agnostic.
// ---------------------------------------------------------------------------

#define NPATCH 4096
#define CDIM   176
#define MMEM   131072
#define KPAD   184                        // padded row (23 x 16B, odd -> conflict-free ldmatrix)
#define TILE_ROWS 128
#define TILE_ELEMS (TILE_ROWS * KPAD)     // 23552 bf16
#define TILE_BYTES (TILE_ELEMS * 2)       // 47104 B
#define NPTILES (NPATCH / TILE_ROWS)      // 32
#define NCHUNKS (MMEM / TILE_ROWS)        // 1024
#define SPLITS  32
#define CHUNKS_PER_CTA (NCHUNKS / SPLITS) // 32
#define KSTEPS  (CDIM / 16)               // 11
#define ROWB    (KPAD * 2)                // 368 bytes per smem row
#define ENC_NEG_INF 0x007FFFFFu

// SMEM layout (dynamic)
#define SM_MB_A   0
#define SM_MB_B0  8
#define SM_MB_B1  16
#define SM_A      1024
#define SM_B0     (SM_A  + TILE_BYTES)    // 48128
#define SM_B1     (SM_B0 + TILE_BYTES)    // 95232
#define SM_TOTAL  (SM_B1 + TILE_BYTES)    // 142336

__device__ __nv_bfloat16 g_pa[NPTILES * TILE_ELEMS];
__device__ __nv_bfloat16 g_mb[(size_t)NCHUNKS * TILE_ELEMS];
__device__ unsigned g_max_enc[NPATCH];

// ---- helpers ---------------------------------------------------------------
__device__ __forceinline__ unsigned enc_f(float f) {
    unsigned u = __float_as_uint(f);
    return (u & 0x80000000u) ? ~u : (u | 0x80000000u);
}
__device__ __forceinline__ float dec_f(unsigned e) {
    unsigned u = (e & 0x80000000u) ? (e & 0x7FFFFFFFu) : ~e;
    return __uint_as_float(u);
}
__device__ __forceinline__ uint32_t smem_u32(const void* p) {
    uint32_t a;
    asm("{ .reg .u64 t; cvta.to.shared.u64 t, %1; cvt.u32.u64 %0, t; }" : "=r"(a) : "l"(p));
    return a;
}

#define MBAR_INIT(a, n) asm volatile("mbarrier.init.shared.b64 [%0], %1;" :: "r"(a), "r"(n) : "memory")
#define MBAR_EXPECT(a, b) asm volatile("mbarrier.arrive.expect_tx.shared.b64 _, [%0], %1;" :: "r"(a), "r"(b) : "memory")
#define MBAR_WAIT(a, ph) do { \
    uint32_t _m = (a), _p = (ph), _d; \
    asm volatile("{\n\t.reg .pred p;\n\tmbarrier.try_wait.parity.acquire.cta.shared::cta.b64 p, [%1], %2;\n\tselp.b32 %0,1,0,p;\n\t}" \
        : "=r"(_d) : "r"(_m), "r"(_p) : "memory"); \
    if (!_d) { \
        asm volatile("{\n\t.reg .pred P1;\n\tWL_%=:\n\tmbarrier.try_wait.parity.acquire.cta.shared::cta.b64 P1, [%0], %1, 0x989680;\n\t@P1 bra.uni WD_%=;\n\tbra.uni WL_%=;\n\tWD_%=:\n\t}" \
            :: "r"(_m), "r"(_p) : "memory"); \
    } } while (0)

__device__ __forceinline__ void bulk_g2s(uint32_t dst, const void* src, uint32_t bytes, uint32_t mbar) {
    asm volatile("cp.async.bulk.shared::cta.global.mbarrier::complete_tx::bytes [%0], [%1], %2, [%3];"
                 :: "r"(dst), "l"(src), "r"(bytes), "r"(mbar) : "memory");
}
__device__ __forceinline__ void ldsm4(uint32_t& r0, uint32_t& r1, uint32_t& r2, uint32_t& r3, uint32_t addr) {
    asm volatile("ldmatrix.sync.aligned.m8n8.x4.shared.b16 {%0,%1,%2,%3}, [%4];"
                 : "=r"(r0), "=r"(r1), "=r"(r2), "=r"(r3) : "r"(addr));
}
__device__ __forceinline__ void mma16816(float* c, const uint32_t* a, const uint32_t* b) {
    asm volatile("mma.sync.aligned.m16n8k16.row.col.f32.bf16.bf16.f32 "
                 "{%0,%1,%2,%3}, {%4,%5,%6,%7}, {%8,%9}, {%0,%1,%2,%3};"
                 : "+f"(c[0]), "+f"(c[1]), "+f"(c[2]), "+f"(c[3])
                 : "r"(a[0]), "r"(a[1]), "r"(a[2]), "r"(a[3]), "r"(b[0]), "r"(b[1]));
}

// ---- prep: normalize rows -> bf16 padded row-major tiles --------------------
__device__ __forceinline__ void prep_rows(const float* __restrict__ src,
                                          __nv_bfloat16* __restrict__ dst, int nrows) {
    int warp = (blockIdx.x * blockDim.x + threadIdx.x) >> 5;
    int lane = threadIdx.x & 31;
    if (warp >= nrows) return;
    const float* row = src + (size_t)warp * CDIM;
    float ss = 0.f;
#pragma unroll
    for (int i = 0; i < 6; i++) {
        int c = lane + 32 * i;
        float x = (c < CDIM) ? row[c] : 0.f;
        ss += x * x;
    }
#pragma unroll
    for (int o = 16; o; o >>= 1) ss += __shfl_xor_sync(0xFFFFFFFFu, ss, o);
    float inv = 1.f / (sqrtf(ss) + 1e-6f);

    int tile = warp >> 7, r = warp & 127;
    __nv_bfloat162* out = (__nv_bfloat162*)(dst + (size_t)tile * TILE_ELEMS + r * KPAD);
#pragma unroll
    for (int kp = lane; kp < KPAD / 2; kp += 32) {
        int k = 2 * kp;
        float x0 = (k     < CDIM) ? row[k]     * inv : 0.f;
        float x1 = (k + 1 < CDIM) ? row[k + 1] * inv : 0.f;
        out[kp] = __floats2bfloat162_rn(x0, x1);
    }
}
__global__ void prep_patches_kernel(const float* __restrict__ in) { prep_rows(in, g_pa, NPATCH); }
__global__ void prep_mem_kernel(const float* __restrict__ in)     { prep_rows(in, g_mb, MMEM); }

__global__ void init_max_kernel() {
    int i = blockIdx.x * blockDim.x + threadIdx.x;
    if (i < NPATCH) g_max_enc[i] = ENC_NEG_INF;
}

// ---- main: HMMA GEMM (128x128 CTA tile) with fused row-max -------------------
// grid (NPTILES, SPLITS), 256 threads = 8 warps (2 m-blocks x 4 n-blocks, 64x32 each)
__global__ void __launch_bounds__(256) hmma_gemm_max_kernel() {
    extern __shared__ char smem[];
    __shared__ unsigned red[TILE_ROWS];
    const uint32_t sb = smem_u32(smem);
    const int tid  = threadIdx.x;
    const int lane = tid & 31;
    const int wid  = tid >> 5;
    const int m0   = (wid & 1) * 64;
    const int n0   = (wid >> 1) * 32;

    if (tid == 0) {
        MBAR_INIT(sb + SM_MB_A, 1);
        MBAR_INIT(sb + SM_MB_B0, 1);
        MBAR_INIT(sb + SM_MB_B1, 1);
    }
    __syncthreads();

    const int ptile = blockIdx.x;
    const int ch0 = blockIdx.y * CHUNKS_PER_CTA;

    if (tid == 0) {
        MBAR_EXPECT(sb + SM_MB_A, TILE_BYTES);
        bulk_g2s(sb + SM_A, g_pa + (size_t)ptile * TILE_ELEMS, TILE_BYTES, sb + SM_MB_A);
        MBAR_EXPECT(sb + SM_MB_B0, TILE_BYTES);
        bulk_g2s(sb + SM_B0, g_mb + (size_t)ch0 * TILE_ELEMS, TILE_BYTES, sb + SM_MB_B0);
        MBAR_EXPECT(sb + SM_MB_B1, TILE_BYTES);
        bulk_g2s(sb + SM_B1, g_mb + (size_t)(ch0 + 1) * TILE_ELEMS, TILE_BYTES, sb + SM_MB_B1);
    }

    // per-lane base byte offsets for ldmatrix
    const uint32_t a_base = sb + SM_A +
        (uint32_t)(m0 + (lane & 15)) * ROWB + ((lane >> 4) << 4);
    const uint32_t b_lane_off =
        (uint32_t)(n0 + ((lane >> 4) << 3) + (lane & 7)) * ROWB + (((lane >> 3) & 1) << 4);

    float rm[4][2];
#pragma unroll
    for (int f = 0; f < 4; f++) { rm[f][0] = -3.0e38f; rm[f][1] = -3.0e38f; }

    bool a_waited = false;

#pragma unroll 1
    for (int c = 0; c < CHUNKS_PER_CTA; c++) {
        const int buf = c & 1;
        const uint32_t ph = (uint32_t)((c >> 1) & 1);
        const uint32_t mb_b = sb + (buf ? SM_MB_B1 : SM_MB_B0);
        const uint32_t b_base = sb + (buf ? SM_B1 : SM_B0) + b_lane_off;

        if (!a_waited) { MBAR_WAIT(sb + SM_MB_A, 0); a_waited = true; }
        MBAR_WAIT(mb_b, ph);

        float acc[4][4][4];
#pragma unroll
        for (int f = 0; f < 4; f++)
#pragma unroll
            for (int g = 0; g < 4; g++)
#pragma unroll
                for (int i = 0; i < 4; i++) acc[f][g][i] = 0.f;

#pragma unroll 1
        for (int ks = 0; ks < KSTEPS; ks++) {
            uint32_t a[4][4], b[4][2];
#pragma unroll
            for (int f = 0; f < 4; f++)
                ldsm4(a[f][0], a[f][1], a[f][2], a[f][3],
                      a_base + (uint32_t)(f * 16) * ROWB + ks * 32);
#pragma unroll
            for (int g2 = 0; g2 < 2; g2++) {
                uint32_t r0, r1, r2, r3;
                ldsm4(r0, r1, r2, r3,
                      b_base + (uint32_t)(g2 * 16) * ROWB + ks * 32);
                b[2 * g2][0] = r0; b[2 * g2][1] = r1;
                b[2 * g2 + 1][0] = r2; b[2 * g2 + 1][1] = r3;
            }
#pragma unroll
            for (int f = 0; f < 4; f++)
#pragma unroll
                for (int g = 0; g < 4; g++)
                    mma16816(acc[f][g], a[f], b[g]);
        }

        __syncthreads();  // all warps done reading this buffer
        if (tid == 0 && c + 2 < CHUNKS_PER_CTA) {
            MBAR_EXPECT(mb_b, TILE_BYTES);
            bulk_g2s(sb + (buf ? SM_B1 : SM_B0),
                     g_mb + (size_t)(ch0 + c + 2) * TILE_ELEMS, TILE_BYTES, mb_b);
        }

        // fold accumulators into running row-max
#pragma unroll
        for (int f = 0; f < 4; f++) {
            float h0 = -3.0e38f, h1 = -3.0e38f;
#pragma unroll
            for (int g = 0; g < 4; g++) {
                h0 = fmaxf(h0, fmaxf(acc[f][g][0], acc[f][g][1]));
                h1 = fmaxf(h1, fmaxf(acc[f][g][2], acc[f][g][3]));
            }
            // reduce across the 4 lanes of the quad (same row, different n)
            h0 = fmaxf(h0, __shfl_xor_sync(0xFFFFFFFFu, h0, 1));
            h0 = fmaxf(h0, __shfl_xor_sync(0xFFFFFFFFu, h0, 2));
            h1 = fmaxf(h1, __shfl_xor_sync(0xFFFFFFFFu, h1, 1));
            h1 = fmaxf(h1, __shfl_xor_sync(0xFFFFFFFFu, h1, 2));
            rm[f][0] = fmaxf(rm[f][0], h0);
            rm[f][1] = fmaxf(rm[f][1], h1);
        }
    }

    // CTA reduction across warps, then one global atomic per row
    if (tid < TILE_ROWS) red[tid] = ENC_NEG_INF;
    __syncthreads();
    if ((lane & 3) == 0) {
#pragma unroll
        for (int f = 0; f < 4; f++) {
            int r = m0 + f * 16 + (lane >> 2);
            atomicMax(&red[r],     enc_f(rm[f][0]));
            atomicMax(&red[r + 8], enc_f(rm[f][1]));
        }
    }
    __syncthreads();
    if (tid < TILE_ROWS) atomicMax(&g_max_enc[ptile * TILE_ROWS + tid], red[tid]);
}

// ---- finalize: scores + top-k mean ------------------------------------------
__global__ void finalize_kernel(const int* __restrict__ topk_ptr,
                                float* __restrict__ out, int out_size) {
    __shared__ float sc[NPATCH];
    __shared__ float rv[256];
    __shared__ int   ri[256];
    const int tid = threadIdx.x;

    for (int i = tid; i < NPATCH; i += 256) {
        float s = 1.0f - dec_f(g_max_enc[i]);
        sc[i] = s;
        if (out_size >= NPATCH) out[i] = s;
    }
    __syncthreads();

    int k = topk_ptr ? *topk_ptr : 10;
    if (k < 1) k = 1;
    if (k > NPATCH) k = NPATCH;

    float sum = 0.f;
    for (int p = 0; p < k; p++) {
        float best = -3.0e38f;
        int bi = 0;
        for (int i = tid; i < NPATCH; i += 256)
            if (sc[i] > best) { best = sc[i]; bi = i; }
        rv[tid] = best; ri[tid] = bi;
        __syncthreads();
        for (int s = 128; s > 0; s >>= 1) {
            if (tid < s && rv[tid + s] > rv[tid]) { rv[tid] = rv[tid + s]; ri[tid] = ri[tid + s]; }
            __syncthreads();
        }
        if (tid == 0) { sum += rv[0]; sc[ri[0]] = -3.0e38f; }
        __syncthreads();
    }

    if (tid == 0) {
        float img = sum / (float)k;
        if (out_size >= NPATCH + 1) out[NPATCH] = img;
        else if (out_size < NPATCH && out_size >= 1) out[0] = img;
    }
}

// ---------------------------------------------------------------------------
extern "C" void kernel_launch(void* const* d_in, const int* in_sizes, int n_in,
                              void* d_out, int out_size) {
    const float* patch = (const float*)d_in[0];
    const float* mem   = (const float*)d_in[1];
    const int*   topk  = (n_in >= 3) ? (const int*)d_in[2] : nullptr;
    float* out = (float*)d_out;
    (void)in_sizes;

    prep_patches_kernel<<<(NPATCH * 32 + 255) / 256, 256>>>(patch);
    prep_mem_kernel<<<(MMEM * 32 + 255) / 256, 256>>>(mem);
    init_max_kernel<<<(NPATCH + 255) / 256, 256>>>();

    cudaFuncSetAttribute(hmma_gemm_max_kernel,
                         cudaFuncAttributeMaxDynamicSharedMemorySize, SM_TOTAL);
    dim3 grid(NPTILES, SPLITS);
    hmma_gemm_max_kernel<<<grid, 256, SM_TOTAL>>>();

    finalize_kernel<<<1, 256>>>(topk, out, out_size);
}

// round 4
// speedup vs baseline: 13.7297x; 1.0662x over previous
#include <cuda_runtime.h>
#include <cuda_bf16.h>
#include <cstdint>

// ---------------------------------------------------------------------------
// PatchCore scoring via HMMA (mma.sync m16n8k16 bf16, fp32 accum):
//   score[n] = 1 - max_m cos(p_n, mem_m);  image = mean(top-k(score))
// R4: CTA tile 256x128, warp tile 64x64 (MMA:LDSM ratio 4.0)
// ---------------------------------------------------------------------------

#define NPATCH 4096
#define CDIM   176
#define MMEM   131072
#define KPAD   184                        // padded row (23 x 16B, odd -> conflict-free ldmatrix)
#define MTILE  256                        // CTA M tile (patch rows)
#define NTILE  128                        // CTA N tile (memory rows per chunk)
#define A_ELEMS (MTILE * KPAD)            // 47104
#define B_ELEMS (NTILE * KPAD)            // 23552
#define A_BYTES (A_ELEMS * 2)             // 94208
#define B_BYTES (B_ELEMS * 2)             // 47104
#define NPTILES (NPATCH / MTILE)          // 16
#define NCHUNKS (MMEM / NTILE)            // 1024
#define SPLITS  32
#define CHUNKS_PER_CTA (NCHUNKS / SPLITS) // 32
#define KSTEPS  (CDIM / 16)               // 11
#define ROWB    (KPAD * 2)                // 368 bytes per smem row
#define ENC_NEG_INF 0x007FFFFFu

// SMEM layout (dynamic)
#define SM_MB_A   0
#define SM_MB_B0  8
#define SM_MB_B1  16
#define SM_A      1024
#define SM_B0     (SM_A  + A_BYTES)       // 95232
#define SM_B1     (SM_B0 + B_BYTES)       // 142336
#define SM_TOTAL  (SM_B1 + B_BYTES)       // 189440

__device__ __nv_bfloat16 g_pa[NPTILES * A_ELEMS];
__device__ __nv_bfloat16 g_mb[(size_t)NCHUNKS * B_ELEMS];
__device__ unsigned g_max_enc[NPATCH];

// ---- helpers ---------------------------------------------------------------
__device__ __forceinline__ unsigned enc_f(float f) {
    unsigned u = __float_as_uint(f);
    return (u & 0x80000000u) ? ~u : (u | 0x80000000u);
}
__device__ __forceinline__ float dec_f(unsigned e) {
    unsigned u = (e & 0x80000000u) ? (e & 0x7FFFFFFFu) : ~e;
    return __uint_as_float(u);
}
__device__ __forceinline__ uint32_t smem_u32(const void* p) {
    uint32_t a;
    asm("{ .reg .u64 t; cvta.to.shared.u64 t, %1; cvt.u32.u64 %0, t; }" : "=r"(a) : "l"(p));
    return a;
}

#define MBAR_INIT(a, n) asm volatile("mbarrier.init.shared.b64 [%0], %1;" :: "r"(a), "r"(n) : "memory")
#define MBAR_EXPECT(a, b) asm volatile("mbarrier.arrive.expect_tx.shared.b64 _, [%0], %1;" :: "r"(a), "r"(b) : "memory")
#define MBAR_WAIT(a, ph) do { \
    uint32_t _m = (a), _p = (ph), _d; \
    asm volatile("{\n\t.reg .pred p;\n\tmbarrier.try_wait.parity.acquire.cta.shared::cta.b64 p, [%1], %2;\n\tselp.b32 %0,1,0,p;\n\t}" \
        : "=r"(_d) : "r"(_m), "r"(_p) : "memory"); \
    if (!_d) { \
        asm volatile("{\n\t.reg .pred P1;\n\tWL_%=:\n\tmbarrier.try_wait.parity.acquire.cta.shared::cta.b64 P1, [%0], %1, 0x989680;\n\t@P1 bra.uni WD_%=;\n\tbra.uni WL_%=;\n\tWD_%=:\n\t}" \
            :: "r"(_m), "r"(_p) : "memory"); \
    } } while (0)

__device__ __forceinline__ void bulk_g2s(uint32_t dst, const void* src, uint32_t bytes, uint32_t mbar) {
    asm volatile("cp.async.bulk.shared::cta.global.mbarrier::complete_tx::bytes [%0], [%1], %2, [%3];"
                 :: "r"(dst), "l"(src), "r"(bytes), "r"(mbar) : "memory");
}
__device__ __forceinline__ void ldsm4(uint32_t& r0, uint32_t& r1, uint32_t& r2, uint32_t& r3, uint32_t addr) {
    asm volatile("ldmatrix.sync.aligned.m8n8.x4.shared.b16 {%0,%1,%2,%3}, [%4];"
                 : "=r"(r0), "=r"(r1), "=r"(r2), "=r"(r3) : "r"(addr));
}
__device__ __forceinline__ void mma16816(float* c, const uint32_t* a, const uint32_t* b) {
    asm volatile("mma.sync.aligned.m16n8k16.row.col.f32.bf16.bf16.f32 "
                 "{%0,%1,%2,%3}, {%4,%5,%6,%7}, {%8,%9}, {%0,%1,%2,%3};"
                 : "+f"(c[0]), "+f"(c[1]), "+f"(c[2]), "+f"(c[3])
                 : "r"(a[0]), "r"(a[1]), "r"(a[2]), "r"(a[3]), "r"(b[0]), "r"(b[1]));
}

// ---- prep: normalize rows -> bf16 padded row-major tiles --------------------
// A tiles are MTILE rows, B tiles NTILE rows
template <int TR>
__device__ __forceinline__ void prep_rows(const float* __restrict__ src,
                                          __nv_bfloat16* __restrict__ dst, int nrows) {
    int warp = (blockIdx.x * blockDim.x + threadIdx.x) >> 5;
    int lane = threadIdx.x & 31;
    if (warp >= nrows) return;
    const float* row = src + (size_t)warp * CDIM;
    float ss = 0.f;
#pragma unroll
    for (int i = 0; i < 6; i++) {
        int c = lane + 32 * i;
        float x = (c < CDIM) ? row[c] : 0.f;
        ss += x * x;
    }
#pragma unroll
    for (int o = 16; o; o >>= 1) ss += __shfl_xor_sync(0xFFFFFFFFu, ss, o);
    float inv = 1.f / (sqrtf(ss) + 1e-6f);

    int tile = warp / TR, r = warp % TR;
    __nv_bfloat162* out = (__nv_bfloat162*)(dst + (size_t)tile * (TR * KPAD) + r * KPAD);
#pragma unroll
    for (int kp = lane; kp < KPAD / 2; kp += 32) {
        int k = 2 * kp;
        float x0 = (k     < CDIM) ? row[k]     * inv : 0.f;
        float x1 = (k + 1 < CDIM) ? row[k + 1] * inv : 0.f;
        out[kp] = __floats2bfloat162_rn(x0, x1);
    }
}
__global__ void prep_patches_kernel(const float* __restrict__ in) { prep_rows<MTILE>(in, g_pa, NPATCH); }
__global__ void prep_mem_kernel(const float* __restrict__ in)     { prep_rows<NTILE>(in, g_mb, MMEM); }

__global__ void init_max_kernel() {
    int i = blockIdx.x * blockDim.x + threadIdx.x;
    if (i < NPATCH) g_max_enc[i] = ENC_NEG_INF;
}

// ---- main: HMMA GEMM (256x128 CTA tile) with fused row-max -------------------
// grid (NPTILES, SPLITS), 256 threads = 8 warps in 4(m) x 2(n), warp tile 64x64
__global__ void __launch_bounds__(256, 1) hmma_gemm_max_kernel() {
    extern __shared__ char smem[];
    __shared__ unsigned red[MTILE];
    const uint32_t sb = smem_u32(smem);
    const int tid  = threadIdx.x;
    const int lane = tid & 31;
    const int wid  = tid >> 5;
    const int m0   = (wid >> 1) * 64;
    const int n0   = (wid & 1) * 64;

    if (tid == 0) {
        MBAR_INIT(sb + SM_MB_A, 1);
        MBAR_INIT(sb + SM_MB_B0, 1);
        MBAR_INIT(sb + SM_MB_B1, 1);
    }
    __syncthreads();

    const int ptile = blockIdx.x;
    const int ch0 = blockIdx.y * CHUNKS_PER_CTA;

    if (tid == 0) {
        MBAR_EXPECT(sb + SM_MB_A, A_BYTES);
        bulk_g2s(sb + SM_A, g_pa + (size_t)ptile * A_ELEMS, A_BYTES, sb + SM_MB_A);
        MBAR_EXPECT(sb + SM_MB_B0, B_BYTES);
        bulk_g2s(sb + SM_B0, g_mb + (size_t)ch0 * B_ELEMS, B_BYTES, sb + SM_MB_B0);
        MBAR_EXPECT(sb + SM_MB_B1, B_BYTES);
        bulk_g2s(sb + SM_B1, g_mb + (size_t)(ch0 + 1) * B_ELEMS, B_BYTES, sb + SM_MB_B1);
    }

    // per-lane base byte offsets for ldmatrix
    const uint32_t a_base = sb + SM_A +
        (uint32_t)(m0 + (lane & 15)) * ROWB + ((lane >> 4) << 4);
    const uint32_t b_lane_off =
        (uint32_t)(n0 + ((lane >> 4) << 3) + (lane & 7)) * ROWB + (((lane >> 3) & 1) << 4);

    float rm[4][2];
#pragma unroll
    for (int f = 0; f < 4; f++) { rm[f][0] = -3.0e38f; rm[f][1] = -3.0e38f; }

    bool a_waited = false;

#pragma unroll 1
    for (int c = 0; c < CHUNKS_PER_CTA; c++) {
        const int buf = c & 1;
        const uint32_t ph = (uint32_t)((c >> 1) & 1);
        const uint32_t mb_b = sb + (buf ? SM_MB_B1 : SM_MB_B0);
        const uint32_t b_base = sb + (buf ? SM_B1 : SM_B0) + b_lane_off;

        if (!a_waited) { MBAR_WAIT(sb + SM_MB_A, 0); a_waited = true; }
        MBAR_WAIT(mb_b, ph);

        float acc[4][8][4];
#pragma unroll
        for (int f = 0; f < 4; f++)
#pragma unroll
            for (int g = 0; g < 8; g++)
#pragma unroll
                for (int i = 0; i < 4; i++) acc[f][g][i] = 0.f;

#pragma unroll 1
        for (int ks = 0; ks < KSTEPS; ks++) {
            uint32_t a[4][4], b[8][2];
#pragma unroll
            for (int f = 0; f < 4; f++)
                ldsm4(a[f][0], a[f][1], a[f][2], a[f][3],
                      a_base + (uint32_t)(f * 16) * ROWB + ks * 32);
#pragma unroll
            for (int g2 = 0; g2 < 4; g2++) {
                uint32_t r0, r1, r2, r3;
                ldsm4(r0, r1, r2, r3,
                      b_base + (uint32_t)(g2 * 16) * ROWB + ks * 32);
                b[2 * g2][0] = r0; b[2 * g2][1] = r1;
                b[2 * g2 + 1][0] = r2; b[2 * g2 + 1][1] = r3;
            }
#pragma unroll
            for (int f = 0; f < 4; f++)
#pragma unroll
                for (int g = 0; g < 8; g++)
                    mma16816(acc[f][g], a[f], b[g]);
        }

        __syncthreads();  // all warps done reading this buffer
        if (tid == 0 && c + 2 < CHUNKS_PER_CTA) {
            MBAR_EXPECT(mb_b, B_BYTES);
            bulk_g2s(sb + (buf ? SM_B1 : SM_B0),
                     g_mb + (size_t)(ch0 + c + 2) * B_ELEMS, B_BYTES, mb_b);
        }

        // fold accumulators into running row-max
#pragma unroll
        for (int f = 0; f < 4; f++) {
            float h0 = -3.0e38f, h1 = -3.0e38f;
#pragma unroll
            for (int g = 0; g < 8; g++) {
                h0 = fmaxf(h0, fmaxf(acc[f][g][0], acc[f][g][1]));
                h1 = fmaxf(h1, fmaxf(acc[f][g][2], acc[f][g][3]));
            }
            h0 = fmaxf(h0, __shfl_xor_sync(0xFFFFFFFFu, h0, 1));
            h0 = fmaxf(h0, __shfl_xor_sync(0xFFFFFFFFu, h0, 2));
            h1 = fmaxf(h1, __shfl_xor_sync(0xFFFFFFFFu, h1, 1));
            h1 = fmaxf(h1, __shfl_xor_sync(0xFFFFFFFFu, h1, 2));
            rm[f][0] = fmaxf(rm[f][0], h0);
            rm[f][1] = fmaxf(rm[f][1], h1);
        }
    }

    // CTA reduction across warps (2 n-warps per m-row set), then global atomic
    if (tid < 128) { red[tid] = ENC_NEG_INF; red[tid + 128] = ENC_NEG_INF; }
    __syncthreads();
    if ((lane & 3) == 0) {
#pragma unroll
        for (int f = 0; f < 4; f++) {
            int r = m0 + f * 16 + (lane >> 2);
            atomicMax(&red[r],     enc_f(rm[f][0]));
            atomicMax(&red[r + 8], enc_f(rm[f][1]));
        }
    }
    __syncthreads();
    if (tid < 128) {
        atomicMax(&g_max_enc[ptile * MTILE + tid], red[tid]);
        atomicMax(&g_max_enc[ptile * MTILE + tid + 128], red[tid + 128]);
    }
}

// ---- finalize: scores + top-k mean ------------------------------------------
__global__ void finalize_kernel(const int* __restrict__ topk_ptr,
                                float* __restrict__ out, int out_size) {
    __shared__ float sc[NPATCH];
    __shared__ float rv[256];
    __shared__ int   ri[256];
    const int tid = threadIdx.x;

    for (int i = tid; i < NPATCH; i += 256) {
        float s = 1.0f - dec_f(g_max_enc[i]);
        sc[i] = s;
        if (out_size >= NPATCH) out[i] = s;
    }
    __syncthreads();

    int k = topk_ptr ? *topk_ptr : 10;
    if (k < 1) k = 1;
    if (k > NPATCH) k = NPATCH;

    float sum = 0.f;
    for (int p = 0; p < k; p++) {
        float best = -3.0e38f;
        int bi = 0;
        for (int i = tid; i < NPATCH; i += 256)
            if (sc[i] > best) { best = sc[i]; bi = i; }
        rv[tid] = best; ri[tid] = bi;
        __syncthreads();
        for (int s = 128; s > 0; s >>= 1) {
            if (tid < s && rv[tid + s] > rv[tid]) { rv[tid] = rv[tid + s]; ri[tid] = ri[tid + s]; }
            __syncthreads();
        }
        if (tid == 0) { sum += rv[0]; sc[ri[0]] = -3.0e38f; }
        __syncthreads();
    }

    if (tid == 0) {
        float img = sum / (float)k;
        if (out_size >= NPATCH + 1) out[NPATCH] = img;
        else if (out_size < NPATCH && out_size >= 1) out[0] = img;
    }
}

// ---------------------------------------------------------------------------
extern "C" void kernel_launch(void* const* d_in, const int* in_sizes, int n_in,
                              void* d_out, int out_size) {
    const float* patch = (const float*)d_in[0];
    const float* mem   = (const float*)d_in[1];
    const int*   topk  = (n_in >= 3) ? (const int*)d_in[2] : nullptr;
    float* out = (float*)d_out;
    (void)in_sizes;

    prep_patches_kernel<<<(NPATCH * 32 + 255) / 256, 256>>>(patch);
    prep_mem_kernel<<<(MMEM * 32 + 255) / 256, 256>>>(mem);
    init_max_kernel<<<(NPATCH + 255) / 256, 256>>>();

    cudaFuncSetAttribute(hmma_gemm_max_kernel,
                         cudaFuncAttributeMaxDynamicSharedMemorySize, SM_TOTAL);
    dim3 grid(NPTILES, SPLITS);
    hmma_gemm_max_kernel<<<grid, 256, SM_TOTAL>>>();

    finalize_kernel<<<1, 256>>>(topk, out, out_size);
}

// round 5
// speedup vs baseline: 16.1078x; 1.1732x over previous
#include <cuda_runtime.h>
#include <cuda_bf16.h>
#include <cstdint>

// ---------------------------------------------------------------------------
// PatchCore scoring via HMMA (mma.sync m16n8k16 bf16, fp32 accum):
//   score[n] = 1 - max_m cos(p_n, mem_m);  image = mean(top-k(score))
// R5: grid 1024 (tail 1.2%), barrier-free mainloop (empty mbarriers),
//     shuffle-free per-chunk epilogue.
// ---------------------------------------------------------------------------

#define NPATCH 4096
#define CDIM   176
#define MMEM   131072
#define KPAD   184                        // padded row (23 x 16B, odd -> conflict-free ldmatrix)
#define MTILE  256
#define NTILE  128
#define A_ELEMS (MTILE * KPAD)            // 47104
#define B_ELEMS (NTILE * KPAD)            // 23552
#define A_BYTES (A_ELEMS * 2)             // 94208
#define B_BYTES (B_ELEMS * 2)             // 47104
#define NPTILES (NPATCH / MTILE)          // 16
#define NCHUNKS (MMEM / NTILE)            // 1024
#define SPLITS  64
#define CHUNKS_PER_CTA (NCHUNKS / SPLITS) // 16
#define KSTEPS  (CDIM / 16)               // 11
#define ROWB    (KPAD * 2)                // 368
#define ENC_NEG_INF 0x007FFFFFu

// SMEM layout (dynamic)
#define SM_MB_A   0
#define SM_MB_B0  8
#define SM_MB_B1  16
#define SM_MB_E0  24                      // empty barriers (consumer -> producer)
#define SM_MB_E1  32
#define SM_A      1024
#define SM_B0     (SM_A  + A_BYTES)       // 95232
#define SM_B1     (SM_B0 + B_BYTES)       // 142336
#define SM_TOTAL  (SM_B1 + B_BYTES)       // 189440

__device__ __nv_bfloat16 g_pa[NPTILES * A_ELEMS];
__device__ __nv_bfloat16 g_mb[(size_t)NCHUNKS * B_ELEMS];
__device__ unsigned g_max_enc[NPATCH];

// ---- helpers ---------------------------------------------------------------
__device__ __forceinline__ unsigned enc_f(float f) {
    unsigned u = __float_as_uint(f);
    return (u & 0x80000000u) ? ~u : (u | 0x80000000u);
}
__device__ __forceinline__ float dec_f(unsigned e) {
    unsigned u = (e & 0x80000000u) ? (e & 0x7FFFFFFFu) : ~e;
    return __uint_as_float(u);
}
__device__ __forceinline__ uint32_t smem_u32(const void* p) {
    uint32_t a;
    asm("{ .reg .u64 t; cvta.to.shared.u64 t, %1; cvt.u32.u64 %0, t; }" : "=r"(a) : "l"(p));
    return a;
}

#define MBAR_INIT(a, n) asm volatile("mbarrier.init.shared.b64 [%0], %1;" :: "r"(a), "r"(n) : "memory")
#define MBAR_ARRIVE(a)  asm volatile("mbarrier.arrive.shared.b64 _, [%0];" :: "r"(a) : "memory")
#define MBAR_EXPECT(a, b) asm volatile("mbarrier.arrive.expect_tx.shared.b64 _, [%0], %1;" :: "r"(a), "r"(b) : "memory")
#define MBAR_WAIT(a, ph) do { \
    uint32_t _m = (a), _p = (ph), _d; \
    asm volatile("{\n\t.reg .pred p;\n\tmbarrier.try_wait.parity.acquire.cta.shared::cta.b64 p, [%1], %2;\n\tselp.b32 %0,1,0,p;\n\t}" \
        : "=r"(_d) : "r"(_m), "r"(_p) : "memory"); \
    if (!_d) { \
        asm volatile("{\n\t.reg .pred P1;\n\tWL_%=:\n\tmbarrier.try_wait.parity.acquire.cta.shared::cta.b64 P1, [%0], %1, 0x989680;\n\t@P1 bra.uni WD_%=;\n\tbra.uni WL_%=;\n\tWD_%=:\n\t}" \
            :: "r"(_m), "r"(_p) : "memory"); \
    } } while (0)

__device__ __forceinline__ void bulk_g2s(uint32_t dst, const void* src, uint32_t bytes, uint32_t mbar) {
    asm volatile("cp.async.bulk.shared::cta.global.mbarrier::complete_tx::bytes [%0], [%1], %2, [%3];"
                 :: "r"(dst), "l"(src), "r"(bytes), "r"(mbar) : "memory");
}
__device__ __forceinline__ void ldsm4(uint32_t& r0, uint32_t& r1, uint32_t& r2, uint32_t& r3, uint32_t addr) {
    asm volatile("ldmatrix.sync.aligned.m8n8.x4.shared.b16 {%0,%1,%2,%3}, [%4];"
                 : "=r"(r0), "=r"(r1), "=r"(r2), "=r"(r3) : "r"(addr));
}
__device__ __forceinline__ void mma16816(float* c, const uint32_t* a, const uint32_t* b) {
    asm volatile("mma.sync.aligned.m16n8k16.row.col.f32.bf16.bf16.f32 "
                 "{%0,%1,%2,%3}, {%4,%5,%6,%7}, {%8,%9}, {%0,%1,%2,%3};"
                 : "+f"(c[0]), "+f"(c[1]), "+f"(c[2]), "+f"(c[3])
                 : "r"(a[0]), "r"(a[1]), "r"(a[2]), "r"(a[3]), "r"(b[0]), "r"(b[1]));
}

// ---- prep: normalize rows -> bf16 padded row-major tiles --------------------
template <int TR>
__device__ __forceinline__ void prep_rows(const float* __restrict__ src,
                                          __nv_bfloat16* __restrict__ dst, int nrows) {
    int warp = (blockIdx.x * blockDim.x + threadIdx.x) >> 5;
    int lane = threadIdx.x & 31;
    if (warp >= nrows) return;
    const float* row = src + (size_t)warp * CDIM;
    float ss = 0.f;
#pragma unroll
    for (int i = 0; i < 6; i++) {
        int c = lane + 32 * i;
        float x = (c < CDIM) ? row[c] : 0.f;
        ss += x * x;
    }
#pragma unroll
    for (int o = 16; o; o >>= 1) ss += __shfl_xor_sync(0xFFFFFFFFu, ss, o);
    float inv = 1.f / (sqrtf(ss) + 1e-6f);

    int tile = warp / TR, r = warp % TR;
    __nv_bfloat162* out = (__nv_bfloat162*)(dst + (size_t)tile * (TR * KPAD) + r * KPAD);
#pragma unroll
    for (int kp = lane; kp < KPAD / 2; kp += 32) {
        int k = 2 * kp;
        float x0 = (k     < CDIM) ? row[k]     * inv : 0.f;
        float x1 = (k + 1 < CDIM) ? row[k + 1] * inv : 0.f;
        out[kp] = __floats2bfloat162_rn(x0, x1);
    }
}
__global__ void prep_patches_kernel(const float* __restrict__ in) { prep_rows<MTILE>(in, g_pa, NPATCH); }
__global__ void prep_mem_kernel(const float* __restrict__ in)     { prep_rows<NTILE>(in, g_mb, MMEM); }

__global__ void init_max_kernel() {
    int i = blockIdx.x * blockDim.x + threadIdx.x;
    if (i < NPATCH) g_max_enc[i] = ENC_NEG_INF;
}

// ---- main: HMMA GEMM (256x128 CTA tile), barrier-free mainloop ---------------
// grid (NPTILES, SPLITS), 256 threads = 8 warps in 4(m) x 2(n), warp tile 64x64
__global__ void __launch_bounds__(256, 1) hmma_gemm_max_kernel() {
    extern __shared__ char smem[];
    __shared__ unsigned red[MTILE];
    const uint32_t sb = smem_u32(smem);
    const int tid  = threadIdx.x;
    const int lane = tid & 31;
    const int wid  = tid >> 5;
    const int m0   = (wid >> 1) * 64;
    const int n0   = (wid & 1) * 64;

    if (tid == 0) {
        MBAR_INIT(sb + SM_MB_A, 1);
        MBAR_INIT(sb + SM_MB_B0, 1);
        MBAR_INIT(sb + SM_MB_B1, 1);
        MBAR_INIT(sb + SM_MB_E0, 8);
        MBAR_INIT(sb + SM_MB_E1, 8);
    }
    __syncthreads();

    const int ptile = blockIdx.x;
    const int ch0 = blockIdx.y * CHUNKS_PER_CTA;

    if (tid == 0) {
        MBAR_EXPECT(sb + SM_MB_A, A_BYTES);
        bulk_g2s(sb + SM_A, g_pa + (size_t)ptile * A_ELEMS, A_BYTES, sb + SM_MB_A);
        MBAR_EXPECT(sb + SM_MB_B0, B_BYTES);
        bulk_g2s(sb + SM_B0, g_mb + (size_t)ch0 * B_ELEMS, B_BYTES, sb + SM_MB_B0);
        MBAR_EXPECT(sb + SM_MB_B1, B_BYTES);
        bulk_g2s(sb + SM_B1, g_mb + (size_t)(ch0 + 1) * B_ELEMS, B_BYTES, sb + SM_MB_B1);
    }

    const uint32_t a_base = sb + SM_A +
        (uint32_t)(m0 + (lane & 15)) * ROWB + ((lane >> 4) << 4);
    const uint32_t b_lane_off =
        (uint32_t)(n0 + ((lane >> 4) << 3) + (lane & 7)) * ROWB + (((lane >> 3) & 1) << 4);

    // per-lane running max: rm[f][h] covers acc[f][g][2h],acc[f][g][2h+1] over all g
    float rm[4][2];
#pragma unroll
    for (int f = 0; f < 4; f++) { rm[f][0] = -3.0e38f; rm[f][1] = -3.0e38f; }

    bool a_waited = false;

#pragma unroll 1
    for (int c = 0; c < CHUNKS_PER_CTA; c++) {
        const int buf = c & 1;
        const uint32_t ph = (uint32_t)((c >> 1) & 1);
        const uint32_t mb_b = sb + (buf ? SM_MB_B1 : SM_MB_B0);
        const uint32_t mb_e = sb + (buf ? SM_MB_E1 : SM_MB_E0);
        const uint32_t b_base = sb + (buf ? SM_B1 : SM_B0) + b_lane_off;

        if (!a_waited) { MBAR_WAIT(sb + SM_MB_A, 0); a_waited = true; }
        MBAR_WAIT(mb_b, ph);

        float acc[4][8][4];
#pragma unroll
        for (int f = 0; f < 4; f++)
#pragma unroll
            for (int g = 0; g < 8; g++)
#pragma unroll
                for (int i = 0; i < 4; i++) acc[f][g][i] = 0.f;

#pragma unroll 1
        for (int ks = 0; ks < KSTEPS; ks++) {
            uint32_t a[4][4], b[8][2];
#pragma unroll
            for (int f = 0; f < 4; f++)
                ldsm4(a[f][0], a[f][1], a[f][2], a[f][3],
                      a_base + (uint32_t)(f * 16) * ROWB + ks * 32);
#pragma unroll
            for (int g2 = 0; g2 < 4; g2++) {
                uint32_t r0, r1, r2, r3;
                ldsm4(r0, r1, r2, r3,
                      b_base + (uint32_t)(g2 * 16) * ROWB + ks * 32);
                b[2 * g2][0] = r0; b[2 * g2][1] = r1;
                b[2 * g2 + 1][0] = r2; b[2 * g2 + 1][1] = r3;
            }
#pragma unroll
            for (int f = 0; f < 4; f++)
#pragma unroll
                for (int g = 0; g < 8; g++)
                    mma16816(acc[f][g], a[f], b[g]);
        }

        // this warp is done reading buffer `buf` -> signal producer
        if (lane == 0) MBAR_ARRIVE(mb_e);

        // per-lane fold, no shuffles, no CTA sync
#pragma unroll
        for (int f = 0; f < 4; f++)
#pragma unroll
            for (int g = 0; g < 8; g++) {
                rm[f][0] = fmaxf(rm[f][0], fmaxf(acc[f][g][0], acc[f][g][1]));
                rm[f][1] = fmaxf(rm[f][1], fmaxf(acc[f][g][2], acc[f][g][3]));
            }

        // producer: wait until all 8 warps released this buffer, then prefetch c+2
        if (tid == 0 && c + 2 < CHUNKS_PER_CTA) {
            MBAR_WAIT(mb_e, ph);
            MBAR_EXPECT(mb_b, B_BYTES);
            bulk_g2s(sb + (buf ? SM_B1 : SM_B0),
                     g_mb + (size_t)(ch0 + c + 2) * B_ELEMS, B_BYTES, mb_b);
        }
    }

    // final quad reduction (lanes sharing a row), then CTA + global reduction
#pragma unroll
    for (int f = 0; f < 4; f++) {
#pragma unroll
        for (int h = 0; h < 2; h++) {
            rm[f][h] = fmaxf(rm[f][h], __shfl_xor_sync(0xFFFFFFFFu, rm[f][h], 1));
            rm[f][h] = fmaxf(rm[f][h], __shfl_xor_sync(0xFFFFFFFFu, rm[f][h], 2));
        }
    }

    if (tid < 128) { red[tid] = ENC_NEG_INF; red[tid + 128] = ENC_NEG_INF; }
    __syncthreads();
    if ((lane & 3) == 0) {
#pragma unroll
        for (int f = 0; f < 4; f++) {
            int r = m0 + f * 16 + (lane >> 2);
            atomicMax(&red[r],     enc_f(rm[f][0]));
            atomicMax(&red[r + 8], enc_f(rm[f][1]));
        }
    }
    __syncthreads();
    if (tid < 128) {
        atomicMax(&g_max_enc[ptile * MTILE + tid], red[tid]);
        atomicMax(&g_max_enc[ptile * MTILE + tid + 128], red[tid + 128]);
    }
}

// ---- finalize: scores + top-k mean ------------------------------------------
__global__ void finalize_kernel(const int* __restrict__ topk_ptr,
                                float* __restrict__ out, int out_size) {
    __shared__ float sc[NPATCH];
    __shared__ float rv[256];
    __shared__ int   ri[256];
    const int tid = threadIdx.x;

    for (int i = tid; i < NPATCH; i += 256) {
        float s = 1.0f - dec_f(g_max_enc[i]);
        sc[i] = s;
        if (out_size >= NPATCH) out[i] = s;
    }
    __syncthreads();

    int k = topk_ptr ? *topk_ptr : 10;
    if (k < 1) k = 1;
    if (k > NPATCH) k = NPATCH;

    float sum = 0.f;
    for (int p = 0; p < k; p++) {
        float best = -3.0e38f;
        int bi = 0;
        for (int i = tid; i < NPATCH; i += 256)
            if (sc[i] > best) { best = sc[i]; bi = i; }
        rv[tid] = best; ri[tid] = bi;
        __syncthreads();
        for (int s = 128; s > 0; s >>= 1) {
            if (tid < s && rv[tid + s] > rv[tid]) { rv[tid] = rv[tid + s]; ri[tid] = ri[tid + s]; }
            __syncthreads();
        }
        if (tid == 0) { sum += rv[0]; sc[ri[0]] = -3.0e38f; }
        __syncthreads();
    }

    if (tid == 0) {
        float img = sum / (float)k;
        if (out_size >= NPATCH + 1) out[NPATCH] = img;
        else if (out_size < NPATCH && out_size >= 1) out[0] = img;
    }
}

// ---------------------------------------------------------------------------
extern "C" void kernel_launch(void* const* d_in, const int* in_sizes, int n_in,
                              void* d_out, int out_size) {
    const float* patch = (const float*)d_in[0];
    const float* mem   = (const float*)d_in[1];
    const int*   topk  = (n_in >= 3) ? (const int*)d_in[2] : nullptr;
    float* out = (float*)d_out;
    (void)in_sizes;

    prep_patches_kernel<<<(NPATCH * 32 + 255) / 256, 256>>>(patch);
    prep_mem_kernel<<<(MMEM * 32 + 255) / 256, 256>>>(mem);
    init_max_kernel<<<(NPATCH + 255) / 256, 256>>>();

    cudaFuncSetAttribute(hmma_gemm_max_kernel,
                         cudaFuncAttributeMaxDynamicSharedMemorySize, SM_TOTAL);
    dim3 grid(NPTILES, SPLITS);
    hmma_gemm_max_kernel<<<grid, 256, SM_TOTAL>>>();

    finalize_kernel<<<1, 256>>>(topk, out, out_size);
}

// round 6
// speedup vs baseline: 16.1476x; 1.0025x over previous
#include <cuda_runtime.h>
#include <cuda_bf16.h>
#include <cstdint>

// ---------------------------------------------------------------------------
// PatchCore scoring via HMMA (mma.sync m16n8k16 bf16, fp32 accum):
//   score[n] = 1 - max_m cos(p_n, mem_m);  image = mean(top-k(score))
// R6: persistent CTAs (148), continuous B pipeline across jobs,
//     A reload overlapped with job epilogue via a_full/a_empty mbarriers.
// ---------------------------------------------------------------------------

#define NPATCH 4096
#define CDIM   176
#define MMEM   131072
#define KPAD   184                        // padded row (23 x 16B, odd -> conflict-free ldmatrix)
#define MTILE  256
#define NTILE  128
#define A_ELEMS (MTILE * KPAD)            // 47104
#define B_ELEMS (NTILE * KPAD)            // 23552
#define A_BYTES (A_ELEMS * 2)             // 94208
#define B_BYTES (B_ELEMS * 2)             // 47104
#define NPTILES (NPATCH / MTILE)          // 16
#define NCHUNKS (MMEM / NTILE)            // 1024
#define SPLITS  64
#define CHUNKS_PER_JOB (NCHUNKS / SPLITS) // 16
#define NJOBS   (NPTILES * SPLITS)        // 1024
#define PCTAS   148                       // persistent CTAs (1/SM)
#define KSTEPS  (CDIM / 16)               // 11
#define ROWB    (KPAD * 2)                // 368
#define ENC_NEG_INF 0x007FFFFFu

// SMEM layout (dynamic)
#define SM_MB_A   0                       // A full
#define SM_MB_B0  8
#define SM_MB_B1  16
#define SM_MB_E0  24                      // B empty (8 arrivals)
#define SM_MB_E1  32
#define SM_MB_AE  40                      // A empty (8 arrivals)
#define SM_A      1024
#define SM_B0     (SM_A  + A_BYTES)       // 95232
#define SM_B1     (SM_B0 + B_BYTES)       // 142336
#define SM_TOTAL  (SM_B1 + B_BYTES)       // 189440

__device__ __nv_bfloat16 g_pa[NPTILES * A_ELEMS];
__device__ __nv_bfloat16 g_mb[(size_t)NCHUNKS * B_ELEMS];
__device__ unsigned g_max_enc[NPATCH];

// ---- helpers ---------------------------------------------------------------
__device__ __forceinline__ unsigned enc_f(float f) {
    unsigned u = __float_as_uint(f);
    return (u & 0x80000000u) ? ~u : (u | 0x80000000u);
}
__device__ __forceinline__ float dec_f(unsigned e) {
    unsigned u = (e & 0x80000000u) ? (e & 0x7FFFFFFFu) : ~e;
    return __uint_as_float(u);
}
__device__ __forceinline__ uint32_t smem_u32(const void* p) {
    uint32_t a;
    asm("{ .reg .u64 t; cvta.to.shared.u64 t, %1; cvt.u32.u64 %0, t; }" : "=r"(a) : "l"(p));
    return a;
}

#define MBAR_INIT(a, n) asm volatile("mbarrier.init.shared.b64 [%0], %1;" :: "r"(a), "r"(n) : "memory")
#define MBAR_ARRIVE(a)  asm volatile("mbarrier.arrive.shared.b64 _, [%0];" :: "r"(a) : "memory")
#define MBAR_EXPECT(a, b) asm volatile("mbarrier.arrive.expect_tx.shared.b64 _, [%0], %1;" :: "r"(a), "r"(b) : "memory")
#define MBAR_WAIT(a, ph) do { \
    uint32_t _m = (a), _p = (ph), _d; \
    asm volatile("{\n\t.reg .pred p;\n\tmbarrier.try_wait.parity.acquire.cta.shared::cta.b64 p, [%1], %2;\n\tselp.b32 %0,1,0,p;\n\t}" \
        : "=r"(_d) : "r"(_m), "r"(_p) : "memory"); \
    if (!_d) { \
        asm volatile("{\n\t.reg .pred P1;\n\tWL_%=:\n\tmbarrier.try_wait.parity.acquire.cta.shared::cta.b64 P1, [%0], %1, 0x989680;\n\t@P1 bra.uni WD_%=;\n\tbra.uni WL_%=;\n\tWD_%=:\n\t}" \
            :: "r"(_m), "r"(_p) : "memory"); \
    } } while (0)

__device__ __forceinline__ void bulk_g2s(uint32_t dst, const void* src, uint32_t bytes, uint32_t mbar) {
    asm volatile("cp.async.bulk.shared::cta.global.mbarrier::complete_tx::bytes [%0], [%1], %2, [%3];"
                 :: "r"(dst), "l"(src), "r"(bytes), "r"(mbar) : "memory");
}
__device__ __forceinline__ void ldsm4(uint32_t& r0, uint32_t& r1, uint32_t& r2, uint32_t& r3, uint32_t addr) {
    asm volatile("ldmatrix.sync.aligned.m8n8.x4.shared.b16 {%0,%1,%2,%3}, [%4];"
                 : "=r"(r0), "=r"(r1), "=r"(r2), "=r"(r3) : "r"(addr));
}
__device__ __forceinline__ void mma16816(float* c, const uint32_t* a, const uint32_t* b) {
    asm volatile("mma.sync.aligned.m16n8k16.row.col.f32.bf16.bf16.f32 "
                 "{%0,%1,%2,%3}, {%4,%5,%6,%7}, {%8,%9}, {%0,%1,%2,%3};"
                 : "+f"(c[0]), "+f"(c[1]), "+f"(c[2]), "+f"(c[3])
                 : "r"(a[0]), "r"(a[1]), "r"(a[2]), "r"(a[3]), "r"(b[0]), "r"(b[1]));
}

// ---- prep: normalize rows -> bf16 padded row-major tiles --------------------
template <int TR, bool INIT_MAX>
__device__ __forceinline__ void prep_rows(const float* __restrict__ src,
                                          __nv_bfloat16* __restrict__ dst, int nrows) {
    int warp = (blockIdx.x * blockDim.x + threadIdx.x) >> 5;
    int lane = threadIdx.x & 31;
    if (warp >= nrows) return;
    const float* row = src + (size_t)warp * CDIM;
    float ss = 0.f;
#pragma unroll
    for (int i = 0; i < 6; i++) {
        int c = lane + 32 * i;
        float x = (c < CDIM) ? row[c] : 0.f;
        ss += x * x;
    }
#pragma unroll
    for (int o = 16; o; o >>= 1) ss += __shfl_xor_sync(0xFFFFFFFFu, ss, o);
    float inv = 1.f / (sqrtf(ss) + 1e-6f);

    int tile = warp / TR, r = warp % TR;
    __nv_bfloat162* out = (__nv_bfloat162*)(dst + (size_t)tile * (TR * KPAD) + r * KPAD);
#pragma unroll
    for (int kp = lane; kp < KPAD / 2; kp += 32) {
        int k = 2 * kp;
        float x0 = (k     < CDIM) ? row[k]     * inv : 0.f;
        float x1 = (k + 1 < CDIM) ? row[k + 1] * inv : 0.f;
        out[kp] = __floats2bfloat162_rn(x0, x1);
    }
    if (INIT_MAX && lane == 0) g_max_enc[warp] = ENC_NEG_INF;
}
__global__ void prep_patches_kernel(const float* __restrict__ in) { prep_rows<MTILE, true>(in, g_pa, NPATCH); }
__global__ void prep_mem_kernel(const float* __restrict__ in)     { prep_rows<NTILE, false>(in, g_mb, MMEM); }

// ---- main: persistent HMMA GEMM (256x128 CTA tile) with fused row-max --------
// grid PCTAS, 256 threads = 8 warps in 4(m) x 2(n), warp tile 64x64
__global__ void __launch_bounds__(256, 1) hmma_gemm_max_kernel() {
    extern __shared__ char smem[];
    __shared__ unsigned red[MTILE];
    const uint32_t sb = smem_u32(smem);
    const int tid  = threadIdx.x;
    const int lane = tid & 31;
    const int wid  = tid >> 5;
    const int m0   = (wid >> 1) * 64;
    const int n0   = (wid & 1) * 64;
    const int bid  = blockIdx.x;

    if (tid == 0) {
        MBAR_INIT(sb + SM_MB_A, 1);
        MBAR_INIT(sb + SM_MB_B0, 1);
        MBAR_INIT(sb + SM_MB_B1, 1);
        MBAR_INIT(sb + SM_MB_E0, 8);
        MBAR_INIT(sb + SM_MB_E1, 8);
        MBAR_INIT(sb + SM_MB_AE, 8);
    }
    __syncthreads();

    // initial loads: A for job0, B for seq 0 and 1
    if (tid == 0) {
        MBAR_EXPECT(sb + SM_MB_A, A_BYTES);
        bulk_g2s(sb + SM_A, g_pa + (size_t)(bid >> 6) * A_ELEMS, A_BYTES, sb + SM_MB_A);
        MBAR_EXPECT(sb + SM_MB_B0, B_BYTES);
        bulk_g2s(sb + SM_B0, g_mb + (size_t)((bid & 63) * CHUNKS_PER_JOB) * B_ELEMS,
                 B_BYTES, sb + SM_MB_B0);
        MBAR_EXPECT(sb + SM_MB_B1, B_BYTES);
        bulk_g2s(sb + SM_B1, g_mb + (size_t)((bid & 63) * CHUNKS_PER_JOB + 1) * B_ELEMS,
                 B_BYTES, sb + SM_MB_B1);
    }

    const uint32_t a_base = sb + SM_A +
        (uint32_t)(m0 + (lane & 15)) * ROWB + ((lane >> 4) << 4);
    const uint32_t b_lane_off =
        (uint32_t)(n0 + ((lane >> 4) << 3) + (lane & 7)) * ROWB + (((lane >> 3) & 1) << 4);

    int t = 0;  // continuous B-chunk sequence counter
#pragma unroll 1
    for (int w = 0, job = bid; job < NJOBS; w++, job += PCTAS) {
        const int ptile = job >> 6;
        const int ch0 = (job & 63) * CHUNKS_PER_JOB;

        float rm[4][2];
#pragma unroll
        for (int f = 0; f < 4; f++) { rm[f][0] = -3.0e38f; rm[f][1] = -3.0e38f; }

        // A for this job ready?
        MBAR_WAIT(sb + SM_MB_A, (uint32_t)(w & 1));

#pragma unroll 1
        for (int c = 0; c < CHUNKS_PER_JOB; c++, t++) {
            const int buf = t & 1;
            const uint32_t ph = (uint32_t)((t >> 1) & 1);
            const uint32_t mb_b = sb + (buf ? SM_MB_B1 : SM_MB_B0);
            const uint32_t mb_e = sb + (buf ? SM_MB_E1 : SM_MB_E0);
            const uint32_t b_base = sb + (buf ? SM_B1 : SM_B0) + b_lane_off;

            MBAR_WAIT(mb_b, ph);

            float acc[4][8][4];
#pragma unroll
            for (int f = 0; f < 4; f++)
#pragma unroll
                for (int g = 0; g < 8; g++)
#pragma unroll
                    for (int i = 0; i < 4; i++) acc[f][g][i] = 0.f;

#pragma unroll 1
            for (int ks = 0; ks < KSTEPS; ks++) {
                uint32_t a[4][4], b[8][2];
#pragma unroll
                for (int f = 0; f < 4; f++)
                    ldsm4(a[f][0], a[f][1], a[f][2], a[f][3],
                          a_base + (uint32_t)(f * 16) * ROWB + ks * 32);
#pragma unroll
                for (int g2 = 0; g2 < 4; g2++) {
                    uint32_t r0, r1, r2, r3;
                    ldsm4(r0, r1, r2, r3,
                          b_base + (uint32_t)(g2 * 16) * ROWB + ks * 32);
                    b[2 * g2][0] = r0; b[2 * g2][1] = r1;
                    b[2 * g2 + 1][0] = r2; b[2 * g2 + 1][1] = r3;
                }
#pragma unroll
                for (int f = 0; f < 4; f++)
#pragma unroll
                    for (int g = 0; g < 8; g++)
                        mma16816(acc[f][g], a[f], b[g]);
            }

            // release buffers
            if (lane == 0) {
                MBAR_ARRIVE(mb_e);
                if (c == CHUNKS_PER_JOB - 1) MBAR_ARRIVE(sb + SM_MB_AE);
            }

            // per-lane fold, no shuffles
#pragma unroll
            for (int f = 0; f < 4; f++)
#pragma unroll
                for (int g = 0; g < 8; g++) {
                    rm[f][0] = fmaxf(rm[f][0], fmaxf(acc[f][g][0], acc[f][g][1]));
                    rm[f][1] = fmaxf(rm[f][1], fmaxf(acc[f][g][2], acc[f][g][3]));
                }

            // producer: refill this buffer with seq t+2 (may cross into next job)
            if (tid == 0) {
                const int s = t + 2;
                const int job2 = bid + (s >> 4) * PCTAS;
                if (job2 < NJOBS) {
                    const int gch = (job2 & 63) * CHUNKS_PER_JOB + (s & 15);
                    MBAR_WAIT(mb_e, ph);
                    MBAR_EXPECT(mb_b, B_BYTES);
                    bulk_g2s(sb + (buf ? SM_B1 : SM_B0),
                             g_mb + (size_t)gch * B_ELEMS, B_BYTES, mb_b);
                }
            }
        }

        // overlap next-job A load with epilogue
        if (tid == 0 && job + PCTAS < NJOBS) {
            MBAR_WAIT(sb + SM_MB_AE, (uint32_t)(w & 1));
            MBAR_EXPECT(sb + SM_MB_A, A_BYTES);
            bulk_g2s(sb + SM_A, g_pa + (size_t)((job + PCTAS) >> 6) * A_ELEMS,
                     A_BYTES, sb + SM_MB_A);
        }

        // job epilogue: quad reduce, CTA reduce, global atomics
#pragma unroll
        for (int f = 0; f < 4; f++) {
#pragma unroll
            for (int h = 0; h < 2; h++) {
                rm[f][h] = fmaxf(rm[f][h], __shfl_xor_sync(0xFFFFFFFFu, rm[f][h], 1));
                rm[f][h] = fmaxf(rm[f][h], __shfl_xor_sync(0xFFFFFFFFu, rm[f][h], 2));
            }
        }
        if (tid < 128) { red[tid] = ENC_NEG_INF; red[tid + 128] = ENC_NEG_INF; }
        __syncthreads();
        if ((lane & 3) == 0) {
#pragma unroll
            for (int f = 0; f < 4; f++) {
                int r = m0 + f * 16 + (lane >> 2);
                atomicMax(&red[r],     enc_f(rm[f][0]));
                atomicMax(&red[r + 8], enc_f(rm[f][1]));
            }
        }
        __syncthreads();
        if (tid < 128) {
            atomicMax(&g_max_enc[ptile * MTILE + tid], red[tid]);
            atomicMax(&g_max_enc[ptile * MTILE + tid + 128], red[tid + 128]);
        }
        __syncthreads();  // red[] reused next job
    }
}

// ---- finalize: scores + top-k mean ------------------------------------------
__global__ void finalize_kernel(const int* __restrict__ topk_ptr,
                                float* __restrict__ out, int out_size) {
    __shared__ float sc[NPATCH];
    __shared__ float rv[256];
    __shared__ int   ri[256];
    const int tid = threadIdx.x;

    for (int i = tid; i < NPATCH; i += 256) {
        float s = 1.0f - dec_f(g_max_enc[i]);
        sc[i] = s;
        if (out_size >= NPATCH) out[i] = s;
    }
    __syncthreads();

    int k = topk_ptr ? *topk_ptr : 10;
    if (k < 1) k = 1;
    if (k > NPATCH) k = NPATCH;

    float sum = 0.f;
    for (int p = 0; p < k; p++) {
        float best = -3.0e38f;
        int bi = 0;
        for (int i = tid; i < NPATCH; i += 256)
            if (sc[i] > best) { best = sc[i]; bi = i; }
        rv[tid] = best; ri[tid] = bi;
        __syncthreads();
        for (int s = 128; s > 0; s >>= 1) {
            if (tid < s && rv[tid + s] > rv[tid]) { rv[tid] = rv[tid + s]; ri[tid] = ri[tid + s]; }
            __syncthreads();
        }
        if (tid == 0) { sum += rv[0]; sc[ri[0]] = -3.0e38f; }
        __syncthreads();
    }

    if (tid == 0) {
        float img = sum / (float)k;
        if (out_size >= NPATCH + 1) out[NPATCH] = img;
        else if (out_size < NPATCH && out_size >= 1) out[0] = img;
    }
}

// ---------------------------------------------------------------------------
extern "C" void kernel_launch(void* const* d_in, const int* in_sizes, int n_in,
                              void* d_out, int out_size) {
    const float* patch = (const float*)d_in[0];
    const float* mem   = (const float*)d_in[1];
    const int*   topk  = (n_in >= 3) ? (const int*)d_in[2] : nullptr;
    float* out = (float*)d_out;
    (void)in_sizes;

    prep_patches_kernel<<<(NPATCH * 32 + 255) / 256, 256>>>(patch);
    prep_mem_kernel<<<(MMEM * 32 + 255) / 256, 256>>>(mem);

    cudaFuncSetAttribute(hmma_gemm_max_kernel,
                         cudaFuncAttributeMaxDynamicSharedMemorySize, SM_TOTAL);
    hmma_gemm_max_kernel<<<PCTAS, 256, SM_TOTAL>>>();

    finalize_kernel<<<1, 256>>>(topk, out, out_size);
}

// round 7
// speedup vs baseline: 17.1195x; 1.0602x over previous
#include <cuda_runtime.h>
#include <cuda_bf16.h>
#include <cstdint>

// ---------------------------------------------------------------------------
// PatchCore scoring via HMMA (mma.sync m16n8k16 bf16, fp32 accum):
//   score[n] = 1 - max_m cos(p_n, mem_m);  image = mean(top-k(score))
// R7: mma-with-C zero-init (no acc zero MOVs), early empty-arrive after last
//     ldmatrix, shuffle-based top-k finalize, merged prep kernel.
// ---------------------------------------------------------------------------

#define NPATCH 4096
#define CDIM   176
#define MMEM   131072
#define KPAD   184                        // padded row (23 x 16B, odd -> conflict-free ldmatrix)
#define MTILE  256
#define NTILE  128
#define A_ELEMS (MTILE * KPAD)            // 47104
#define B_ELEMS (NTILE * KPAD)            // 23552
#define A_BYTES (A_ELEMS * 2)             // 94208
#define B_BYTES (B_ELEMS * 2)             // 47104
#define NPTILES (NPATCH / MTILE)          // 16
#define NCHUNKS (MMEM / NTILE)            // 1024
#define SPLITS  64
#define CHUNKS_PER_JOB (NCHUNKS / SPLITS) // 16
#define NJOBS   (NPTILES * SPLITS)        // 1024
#define PCTAS   148
#define KSTEPS  (CDIM / 16)               // 11
#define ROWB    (KPAD * 2)                // 368
#define ENC_NEG_INF 0x007FFFFFu

// SMEM layout (dynamic)
#define SM_MB_A   0                       // A full
#define SM_MB_B0  8
#define SM_MB_B1  16
#define SM_MB_E0  24                      // B empty (8 arrivals)
#define SM_MB_E1  32
#define SM_MB_AE  40                      // A empty (8 arrivals)
#define SM_A      1024
#define SM_B0     (SM_A  + A_BYTES)       // 95232
#define SM_B1     (SM_B0 + B_BYTES)       // 142336
#define SM_TOTAL  (SM_B1 + B_BYTES)       // 189440

__device__ __nv_bfloat16 g_pa[NPTILES * A_ELEMS];
__device__ __nv_bfloat16 g_mb[(size_t)NCHUNKS * B_ELEMS];
__device__ unsigned g_max_enc[NPATCH];

// ---- helpers ---------------------------------------------------------------
__device__ __forceinline__ unsigned enc_f(float f) {
    unsigned u = __float_as_uint(f);
    return (u & 0x80000000u) ? ~u : (u | 0x80000000u);
}
__device__ __forceinline__ float dec_f(unsigned e) {
    unsigned u = (e & 0x80000000u) ? (e & 0x7FFFFFFFu) : ~e;
    return __uint_as_float(u);
}
__device__ __forceinline__ uint32_t smem_u32(const void* p) {
    uint32_t a;
    asm("{ .reg .u64 t; cvta.to.shared.u64 t, %1; cvt.u32.u64 %0, t; }" : "=r"(a) : "l"(p));
    return a;
}

#define MBAR_INIT(a, n) asm volatile("mbarrier.init.shared.b64 [%0], %1;" :: "r"(a), "r"(n) : "memory")
#define MBAR_ARRIVE(a)  asm volatile("mbarrier.arrive.shared.b64 _, [%0];" :: "r"(a) : "memory")
#define MBAR_EXPECT(a, b) asm volatile("mbarrier.arrive.expect_tx.shared.b64 _, [%0], %1;" :: "r"(a), "r"(b) : "memory")
#define MBAR_WAIT(a, ph) do { \
    uint32_t _m = (a), _p = (ph), _d; \
    asm volatile("{\n\t.reg .pred p;\n\tmbarrier.try_wait.parity.acquire.cta.shared::cta.b64 p, [%1], %2;\n\tselp.b32 %0,1,0,p;\n\t}" \
        : "=r"(_d) : "r"(_m), "r"(_p) : "memory"); \
    if (!_d) { \
        asm volatile("{\n\t.reg .pred P1;\n\tWL_%=:\n\tmbarrier.try_wait.parity.acquire.cta.shared::cta.b64 P1, [%0], %1, 0x989680;\n\t@P1 bra.uni WD_%=;\n\tbra.uni WL_%=;\n\tWD_%=:\n\t}" \
            :: "r"(_m), "r"(_p) : "memory"); \
    } } while (0)

__device__ __forceinline__ void bulk_g2s(uint32_t dst, const void* src, uint32_t bytes, uint32_t mbar) {
    asm volatile("cp.async.bulk.shared::cta.global.mbarrier::complete_tx::bytes [%0], [%1], %2, [%3];"
                 :: "r"(dst), "l"(src), "r"(bytes), "r"(mbar) : "memory");
}
__device__ __forceinline__ void ldsm4(uint32_t& r0, uint32_t& r1, uint32_t& r2, uint32_t& r3, uint32_t addr) {
    asm volatile("ldmatrix.sync.aligned.m8n8.x4.shared.b16 {%0,%1,%2,%3}, [%4];"
                 : "=r"(r0), "=r"(r1), "=r"(r2), "=r"(r3) : "r"(addr));
}
__device__ __forceinline__ void mma16816(float* c, const uint32_t* a, const uint32_t* b) {
    asm volatile("mma.sync.aligned.m16n8k16.row.col.f32.bf16.bf16.f32 "
                 "{%0,%1,%2,%3}, {%4,%5,%6,%7}, {%8,%9}, {%0,%1,%2,%3};"
                 : "+f"(c[0]), "+f"(c[1]), "+f"(c[2]), "+f"(c[3])
                 : "r"(a[0]), "r"(a[1]), "r"(a[2]), "r"(a[3]), "r"(b[0]), "r"(b[1]));
}
// first k-step: D = A*B + 0 (no accumulator zero-init MOVs)
__device__ __forceinline__ void mma16816_c0(float* c, const uint32_t* a, const uint32_t* b, float z) {
    asm volatile("mma.sync.aligned.m16n8k16.row.col.f32.bf16.bf16.f32 "
                 "{%0,%1,%2,%3}, {%4,%5,%6,%7}, {%8,%9}, {%10,%10,%10,%10};"
                 : "=f"(c[0]), "=f"(c[1]), "=f"(c[2]), "=f"(c[3])
                 : "r"(a[0]), "r"(a[1]), "r"(a[2]), "r"(a[3]), "r"(b[0]), "r"(b[1]), "f"(z));
}

// ---- prep: normalize rows -> bf16 padded row-major tiles (merged) -----------
__device__ __forceinline__ void prep_one_row(const float* __restrict__ row,
                                             __nv_bfloat16* __restrict__ out_row, int lane) {
    float ss = 0.f;
    float v[6];
#pragma unroll
    for (int i = 0; i < 6; i++) {
        int c = lane + 32 * i;
        float x = (c < CDIM) ? row[c] : 0.f;
        v[i] = x;
        ss += x * x;
    }
#pragma unroll
    for (int o = 16; o; o >>= 1) ss += __shfl_xor_sync(0xFFFFFFFFu, ss, o);
    float inv = 1.f / (sqrtf(ss) + 1e-6f);
    __nv_bfloat162* out = (__nv_bfloat162*)out_row;
#pragma unroll
    for (int kp = lane; kp < KPAD / 2; kp += 32) {
        int k = 2 * kp;
        float x0 = (k     < CDIM) ? row[k]     * inv : 0.f;
        float x1 = (k + 1 < CDIM) ? row[k + 1] * inv : 0.f;
        out[kp] = __floats2bfloat162_rn(x0, x1);
    }
    (void)v;
}

__global__ void prep_all_kernel(const float* __restrict__ patch,
                                const float* __restrict__ mem) {
    int warp = (blockIdx.x * blockDim.x + threadIdx.x) >> 5;
    int lane = threadIdx.x & 31;
    if (warp < NPATCH) {
        int tile = warp / MTILE, r = warp % MTILE;
        prep_one_row(patch + (size_t)warp * CDIM,
                     g_pa + (size_t)tile * A_ELEMS + (size_t)r * KPAD, lane);
        if (lane == 0) g_max_enc[warp] = ENC_NEG_INF;
    } else if (warp < NPATCH + MMEM) {
        int m = warp - NPATCH;
        int tile = m / NTILE, r = m % NTILE;
        prep_one_row(mem + (size_t)m * CDIM,
                     g_mb + (size_t)tile * B_ELEMS + (size_t)r * KPAD, lane);
    }
}

// ---- main: persistent HMMA GEMM (256x128 CTA tile) with fused row-max --------
__global__ void __launch_bounds__(256, 1) hmma_gemm_max_kernel() {
    extern __shared__ char smem[];
    __shared__ unsigned red[MTILE];
    const uint32_t sb = smem_u32(smem);
    const int tid  = threadIdx.x;
    const int lane = tid & 31;
    const int wid  = tid >> 5;
    const int m0   = (wid >> 1) * 64;
    const int n0   = (wid & 1) * 64;
    const int bid  = blockIdx.x;

    if (tid == 0) {
        MBAR_INIT(sb + SM_MB_A, 1);
        MBAR_INIT(sb + SM_MB_B0, 1);
        MBAR_INIT(sb + SM_MB_B1, 1);
        MBAR_INIT(sb + SM_MB_E0, 8);
        MBAR_INIT(sb + SM_MB_E1, 8);
        MBAR_INIT(sb + SM_MB_AE, 8);
    }
    __syncthreads();

    if (tid == 0) {
        MBAR_EXPECT(sb + SM_MB_A, A_BYTES);
        bulk_g2s(sb + SM_A, g_pa + (size_t)(bid >> 6) * A_ELEMS, A_BYTES, sb + SM_MB_A);
        MBAR_EXPECT(sb + SM_MB_B0, B_BYTES);
        bulk_g2s(sb + SM_B0, g_mb + (size_t)((bid & 63) * CHUNKS_PER_JOB) * B_ELEMS,
                 B_BYTES, sb + SM_MB_B0);
        MBAR_EXPECT(sb + SM_MB_B1, B_BYTES);
        bulk_g2s(sb + SM_B1, g_mb + (size_t)((bid & 63) * CHUNKS_PER_JOB + 1) * B_ELEMS,
                 B_BYTES, sb + SM_MB_B1);
    }

    const uint32_t a_base = sb + SM_A +
        (uint32_t)(m0 + (lane & 15)) * ROWB + ((lane >> 4) << 4);
    const uint32_t b_lane_off =
        (uint32_t)(n0 + ((lane >> 4) << 3) + (lane & 7)) * ROWB + (((lane >> 3) & 1) << 4);

    int t = 0;  // continuous B-chunk sequence counter
#pragma unroll 1
    for (int w = 0, job = bid; job < NJOBS; w++, job += PCTAS) {
        const int ptile = job >> 6;

        float rm[4][2];
#pragma unroll
        for (int f = 0; f < 4; f++) { rm[f][0] = -3.0e38f; rm[f][1] = -3.0e38f; }

        MBAR_WAIT(sb + SM_MB_A, (uint32_t)(w & 1));

#pragma unroll 1
        for (int c = 0; c < CHUNKS_PER_JOB; c++, t++) {
            const int buf = t & 1;
            const uint32_t ph = (uint32_t)((t >> 1) & 1);
            const uint32_t mb_b = sb + (buf ? SM_MB_B1 : SM_MB_B0);
            const uint32_t mb_e = sb + (buf ? SM_MB_E1 : SM_MB_E0);
            const uint32_t b_base = sb + (buf ? SM_B1 : SM_B0) + b_lane_off;

            MBAR_WAIT(mb_b, ph);

            float acc[4][8][4];
            uint32_t a[4][4], b[8][2];

#define LOAD_FRAGS(ks) do {                                                     \
    _Pragma("unroll")                                                           \
    for (int f = 0; f < 4; f++)                                                 \
        ldsm4(a[f][0], a[f][1], a[f][2], a[f][3],                               \
              a_base + (uint32_t)(f * 16) * ROWB + (ks) * 32);                  \
    _Pragma("unroll")                                                           \
    for (int g2 = 0; g2 < 4; g2++) {                                            \
        uint32_t r0, r1, r2, r3;                                                \
        ldsm4(r0, r1, r2, r3,                                                   \
              b_base + (uint32_t)(g2 * 16) * ROWB + (ks) * 32);                 \
        b[2 * g2][0] = r0; b[2 * g2][1] = r1;                                   \
        b[2 * g2 + 1][0] = r2; b[2 * g2 + 1][1] = r3;                           \
    } } while (0)

            // ks = 0: init accumulators directly from MMA (C = 0)
            LOAD_FRAGS(0);
#pragma unroll
            for (int f = 0; f < 4; f++)
#pragma unroll
                for (int g = 0; g < 8; g++)
                    mma16816_c0(acc[f][g], a[f], b[g], 0.0f);

            // ks = 1..9
#pragma unroll 1
            for (int ks = 1; ks < KSTEPS - 1; ks++) {
                LOAD_FRAGS(ks);
#pragma unroll
                for (int f = 0; f < 4; f++)
#pragma unroll
                    for (int g = 0; g < 8; g++)
                        mma16816(acc[f][g], a[f], b[g]);
            }

            // ks = 10: last fragment loads, then release buffers BEFORE tail MMAs
            LOAD_FRAGS(KSTEPS - 1);
            if (lane == 0) {
                MBAR_ARRIVE(mb_e);
                if (c == CHUNKS_PER_JOB - 1) MBAR_ARRIVE(sb + SM_MB_AE);
            }
#pragma unroll
            for (int f = 0; f < 4; f++)
#pragma unroll
                for (int g = 0; g < 8; g++)
                    mma16816(acc[f][g], a[f], b[g]);
#undef LOAD_FRAGS

            // per-lane fold
#pragma unroll
            for (int f = 0; f < 4; f++)
#pragma unroll
                for (int g = 0; g < 8; g++) {
                    rm[f][0] = fmaxf(rm[f][0], fmaxf(acc[f][g][0], acc[f][g][1]));
                    rm[f][1] = fmaxf(rm[f][1], fmaxf(acc[f][g][2], acc[f][g][3]));
                }

            // producer: refill this buffer with seq t+2 (may cross into next job)
            if (tid == 0) {
                const int s = t + 2;
                const int job2 = bid + (s >> 4) * PCTAS;
                if (job2 < NJOBS) {
                    const int gch = (job2 & 63) * CHUNKS_PER_JOB + (s & 15);
                    MBAR_WAIT(mb_e, ph);
                    MBAR_EXPECT(mb_b, B_BYTES);
                    bulk_g2s(sb + (buf ? SM_B1 : SM_B0),
                             g_mb + (size_t)gch * B_ELEMS, B_BYTES, mb_b);
                }
            }
        }

        // overlap next-job A load with epilogue
        if (tid == 0 && job + PCTAS < NJOBS) {
            MBAR_WAIT(sb + SM_MB_AE, (uint32_t)(w & 1));
            MBAR_EXPECT(sb + SM_MB_A, A_BYTES);
            bulk_g2s(sb + SM_A, g_pa + (size_t)((job + PCTAS) >> 6) * A_ELEMS,
                     A_BYTES, sb + SM_MB_A);
        }

        // job epilogue: quad reduce, CTA reduce, global atomics
#pragma unroll
        for (int f = 0; f < 4; f++) {
#pragma unroll
            for (int h = 0; h < 2; h++) {
                rm[f][h] = fmaxf(rm[f][h], __shfl_xor_sync(0xFFFFFFFFu, rm[f][h], 1));
                rm[f][h] = fmaxf(rm[f][h], __shfl_xor_sync(0xFFFFFFFFu, rm[f][h], 2));
            }
        }
        if (tid < 128) { red[tid] = ENC_NEG_INF; red[tid + 128] = ENC_NEG_INF; }
        __syncthreads();
        if ((lane & 3) == 0) {
#pragma unroll
            for (int f = 0; f < 4; f++) {
                int r = m0 + f * 16 + (lane >> 2);
                atomicMax(&red[r],     enc_f(rm[f][0]));
                atomicMax(&red[r + 8], enc_f(rm[f][1]));
            }
        }
        __syncthreads();
        if (tid < 128) {
            atomicMax(&g_max_enc[ptile * MTILE + tid], red[tid]);
            atomicMax(&g_max_enc[ptile * MTILE + tid + 128], red[tid + 128]);
        }
        __syncthreads();
    }
}

// ---- finalize: scores + top-k mean (shuffle-based selection) -----------------
__global__ void finalize_kernel(const int* __restrict__ topk_ptr,
                                float* __restrict__ out, int out_size) {
    __shared__ float sc[NPATCH];
    __shared__ unsigned long long wb[8];
    const int tid  = threadIdx.x;
    const int lane = tid & 31;
    const int wid  = tid >> 5;

    for (int i = tid; i < NPATCH; i += 256) {
        float s = 1.0f - dec_f(g_max_enc[i]);
        sc[i] = s;
        if (out_size >= NPATCH) out[i] = s;
    }
    __syncthreads();

    int k = topk_ptr ? *topk_ptr : 10;
    if (k < 1) k = 1;
    if (k > NPATCH) k = NPATCH;

    float sum = 0.f;
    for (int p = 0; p < k; p++) {
        float best = -3.0e38f;
        int bi = 0;
#pragma unroll
        for (int i = tid; i < NPATCH; i += 256)
            if (sc[i] > best) { best = sc[i]; bi = i; }
        unsigned long long pk = ((unsigned long long)enc_f(best) << 32) | (unsigned)bi;
#pragma unroll
        for (int o = 16; o; o >>= 1) {
            unsigned long long q = __shfl_xor_sync(0xFFFFFFFFu, pk, o);
            if (q > pk) pk = q;
        }
        if (lane == 0) wb[wid] = pk;
        __syncthreads();
        if (tid == 0) {
            unsigned long long m = wb[0];
#pragma unroll
            for (int w2 = 1; w2 < 8; w2++) if (wb[w2] > m) m = wb[w2];
            sum += dec_f((unsigned)(m >> 32));
            sc[(unsigned)m & 0xFFFFFFFFu] = -3.0e38f;
        }
        __syncthreads();
    }

    if (tid == 0) {
        float img = sum / (float)k;
        if (out_size >= NPATCH + 1) out[NPATCH] = img;
        else if (out_size < NPATCH && out_size >= 1) out[0] = img;
    }
}

// ---------------------------------------------------------------------------
extern "C" void kernel_launch(void* const* d_in, const int* in_sizes, int n_in,
                              void* d_out, int out_size) {
    const float* patch = (const float*)d_in[0];
    const float* mem   = (const float*)d_in[1];
    const int*   topk  = (n_in >= 3) ? (const int*)d_in[2] : nullptr;
    float* out = (float*)d_out;
    (void)in_sizes;

    const int total_warps = NPATCH + MMEM;
    prep_all_kernel<<<(total_warps * 32 + 255) / 256, 256>>>(patch, mem);

    cudaFuncSetAttribute(hmma_gemm_max_kernel,
                         cudaFuncAttributeMaxDynamicSharedMemorySize, SM_TOTAL);
    hmma_gemm_max_kernel<<<PCTAS, 256, SM_TOTAL>>>();

    finalize_kernel<<<1, 256>>>(topk, out, out_size);
}